// round 14
// baseline (speedup 1.0000x reference)
#include <cuda_runtime.h>
#include <cuda_fp16.h>

#define N_MAX   100000
#define E_MAX   1600000
#define NFEAT   128
#define NHID    64
#define NCLS    40

// ---------------- device scratch (allocation-free) ----------------
// All feature arrays 128B-aligned; h2/a2 rows PADDED to 128B (8 uint4)
// so every 5-lane 80B access stays within one L1 cacheline.
__device__ int g_is64;
__device__ int g_deg[N_MAX];
__device__ __align__(128) uint4 g_h1h[N_MAX * 8];   // h1  [N,64] fp16, 128B rows
__device__ __align__(128) uint4 g_a1h[N_MAX * 8];   // agg1[N,64] fp16 (REDG)
__device__ __align__(128) uint4 g_h2h[N_MAX * 8];   // h2  [N,40] fp16, 128B-padded rows
__device__ __align__(128) uint4 g_a2h[N_MAX * 8];   // agg2[N,40] fp16 (REDG)

static __device__ __forceinline__ unsigned smem_u32(const void* p) {
    return (unsigned)__cvta_generic_to_shared(p);
}

// ====== GEMM1 (tensor core): h1 = x @ W1^T + b1 -> [N,64] fp16 =======
__global__ __launch_bounds__(256) void k_gemm1(
    const float* __restrict__ x, const float* __restrict__ W,
    const float* __restrict__ b, const unsigned* __restrict__ ei, int n)
{
    // -- housekeeping prologue --
    int gid = blockIdx.x * 256 + threadIdx.x;
    if (gid < n) g_deg[gid] = 0;
    if (gid == 0) {
        unsigned hi = 0;
        #pragma unroll
        for (int j = 1; j < 64; j += 2) hi |= ei[j];
        g_is64 = (hi == 0u) ? 1 : 0;
    }

    __shared__ __align__(16) __half xs[128][72];
    __shared__ __align__(16) __half ws[64][72];
    int tid  = threadIdx.x;
    int warp = tid >> 5, lane = tid & 31;
    int row0 = blockIdx.x * 128;
    int m0   = warp * 16;

    float acc[8][4];
    #pragma unroll
    for (int j = 0; j < 8; ++j)
        #pragma unroll
        for (int i = 0; i < 4; ++i) acc[j][i] = 0.f;

    for (int kc = 0; kc < 2; ++kc) {
        int k0g = kc * 64;
        #pragma unroll
        for (int i = 0; i < 8; ++i) {
            int idx = tid + i * 256;
            int r = idx >> 4, c4 = idx & 15;
            float4 v = make_float4(0.f, 0.f, 0.f, 0.f);
            if (row0 + r < n)
                v = __ldg((const float4*)(x + (size_t)(row0 + r) * NFEAT + k0g) + c4);
            *(__half2*)&xs[r][c4 * 4]     = __floats2half2_rn(v.x, v.y);
            *(__half2*)&xs[r][c4 * 4 + 2] = __floats2half2_rn(v.z, v.w);
        }
        #pragma unroll
        for (int i = 0; i < 4; ++i) {
            int idx = tid + i * 256;
            int r = idx >> 4, c4 = idx & 15;
            float4 v = __ldg((const float4*)(W + (size_t)r * NFEAT + k0g) + c4);
            *(__half2*)&ws[r][c4 * 4]     = __floats2half2_rn(v.x, v.y);
            *(__half2*)&ws[r][c4 * 4 + 2] = __floats2half2_rn(v.z, v.w);
        }
        __syncthreads();

        #pragma unroll
        for (int kk = 0; kk < 4; ++kk) {
            int k0 = kk * 16;
            unsigned a0, a1, a2, a3;
            {
                int r = m0 + (lane & 7) + ((lane >> 3) & 1) * 8;
                int c = k0 + (lane >> 4) * 8;
                unsigned addr = smem_u32(&xs[r][c]);
                asm volatile(
                    "ldmatrix.sync.aligned.m8n8.x4.shared.b16 {%0,%1,%2,%3}, [%4];"
                    : "=r"(a0), "=r"(a1), "=r"(a2), "=r"(a3) : "r"(addr));
            }
            #pragma unroll
            for (int j2 = 0; j2 < 4; ++j2) {
                int n0 = j2 * 16;
                unsigned b0, b1, b2, b3;
                {
                    int r = n0 + (lane & 7) + (lane >> 4) * 8;
                    int c = k0 + ((lane >> 3) & 1) * 8;
                    unsigned addr = smem_u32(&ws[r][c]);
                    asm volatile(
                        "ldmatrix.sync.aligned.m8n8.x4.shared.b16 {%0,%1,%2,%3}, [%4];"
                        : "=r"(b0), "=r"(b1), "=r"(b2), "=r"(b3) : "r"(addr));
                }
                float* c0 = acc[j2 * 2];
                asm volatile(
                    "mma.sync.aligned.m16n8k16.row.col.f32.f16.f16.f32 "
                    "{%0,%1,%2,%3}, {%4,%5,%6,%7}, {%8,%9}, {%0,%1,%2,%3};"
                    : "+f"(c0[0]), "+f"(c0[1]), "+f"(c0[2]), "+f"(c0[3])
                    : "r"(a0), "r"(a1), "r"(a2), "r"(a3), "r"(b0), "r"(b1));
                float* c1 = acc[j2 * 2 + 1];
                asm volatile(
                    "mma.sync.aligned.m16n8k16.row.col.f32.f16.f16.f32 "
                    "{%0,%1,%2,%3}, {%4,%5,%6,%7}, {%8,%9}, {%0,%1,%2,%3};"
                    : "+f"(c1[0]), "+f"(c1[1]), "+f"(c1[2]), "+f"(c1[3])
                    : "r"(a0), "r"(a1), "r"(a2), "r"(a3), "r"(b2), "r"(b3));
            }
        }
        __syncthreads();
    }

    int rA = row0 + m0 + (lane >> 2);
    int rB = rA + 8;
    #pragma unroll
    for (int j = 0; j < 8; ++j) {
        int nn = j * 8 + (lane & 3) * 2;
        float bx = __ldg(&b[nn]), by = __ldg(&b[nn + 1]);
        if (rA < n) {
            __half2 h = __floats2half2_rn(acc[j][0] + bx, acc[j][1] + by);
            unsigned wv = *(unsigned*)&h;
            ((unsigned*)g_h1h)[rA * 32 + nn / 2] = wv;
            ((unsigned*)g_a1h)[rA * 32 + nn / 2] = wv;
        }
        if (rB < n) {
            __half2 h = __floats2half2_rn(acc[j][2] + bx, acc[j][3] + by);
            unsigned wv = *(unsigned*)&h;
            ((unsigned*)g_h1h)[rB * 32 + nn / 2] = wv;
            ((unsigned*)g_a1h)[rB * 32 + nn / 2] = wv;
        }
    }
}

// ====== scatter1: agg1[dst] += h1[src], ILP-4 (16 edges/warp) ========
// 4 groups of 8 lanes; each group handles edges e0, e0+4, e0+8, e0+12.
__global__ __launch_bounds__(256) void k_scatter1(const void* __restrict__ ei, int E) {
    int t = blockIdx.x * blockDim.x + threadIdx.x;
    int warpid = t >> 5;
    int lane = t & 31;
    int grp = lane >> 3, sub = lane & 7;
    int eb = warpid * 16 + grp;
    if (eb >= E) return;

    int s[4], d[4];
    bool ok[4];
    #pragma unroll
    for (int j = 0; j < 4; ++j) {
        int e = eb + j * 4;
        ok[j] = (e < E);
    }
    if (g_is64) {
        const long long* p = (const long long*)ei;
        #pragma unroll
        for (int j = 0; j < 4; ++j) if (ok[j]) {
            int e = eb + j * 4;
            s[j] = (int)__ldg(&p[e]); d[j] = (int)__ldg(&p[E + e]);
        }
    } else {
        const int* p = (const int*)ei;
        #pragma unroll
        for (int j = 0; j < 4; ++j) if (ok[j]) {
            int e = eb + j * 4;
            s[j] = __ldg(&p[e]); d[j] = __ldg(&p[E + e]);
        }
    }
    if (sub == 0) {
        #pragma unroll
        for (int j = 0; j < 4; ++j) if (ok[j]) atomicAdd(&g_deg[d[j]], 1);
    }
    uint4 v[4];
    #pragma unroll
    for (int j = 0; j < 4; ++j) if (ok[j])
        v[j] = __ldg(&g_h1h[s[j] * 8 + sub]);
    #pragma unroll
    for (int j = 0; j < 4; ++j) if (ok[j])
        asm volatile("red.global.add.noftz.v4.f16x2 [%0], {%1,%2,%3,%4};"
                     :: "l"(&g_a1h[d[j] * 8 + sub]),
                        "r"(v[j].x), "r"(v[j].y), "r"(v[j].z), "r"(v[j].w) : "memory");
}

// ====== GEMM2 (tensor core): h2 = relu(agg1/(deg+1)) @ W2^T + b2 =====
// M=128 (8 warps x m16), N=40 (5 n8-tiles via 3 B ldmatrix.x4), K=64.
__global__ __launch_bounds__(256) void k_gemm2(
    const float* __restrict__ W, const float* __restrict__ b, int n)
{
    __shared__ __align__(16) __half rs[128][72];
    __shared__ __align__(16) __half ws[48][72];   // rows 40..47 unused pad
    int tid  = threadIdx.x;
    int warp = tid >> 5, lane = tid & 31;
    int row0 = blockIdx.x * 128;
    int m0   = warp * 16;

    // fill rs = relu(agg1 * 1/(deg+1)) in fp16
    #pragma unroll
    for (int i = 0; i < 4; ++i) {
        int idx = tid + i * 256;          // 0..1023
        int r = idx >> 3, c8 = idx & 7;   // 8 uint4 per row
        int row = row0 + r;
        uint4 a = make_uint4(0, 0, 0, 0);
        float iv = 0.f;
        if (row < n) {
            iv = 1.0f / (float)(__ldg(&g_deg[row]) + 1);
            a = g_a1h[row * 8 + c8];
        }
        float2 f;
        f = __half22float2(*(__half2*)&a.x);
        *(__half2*)&rs[r][c8 * 8 + 0] = __floats2half2_rn(fmaxf(f.x * iv, 0.f), fmaxf(f.y * iv, 0.f));
        f = __half22float2(*(__half2*)&a.y);
        *(__half2*)&rs[r][c8 * 8 + 2] = __floats2half2_rn(fmaxf(f.x * iv, 0.f), fmaxf(f.y * iv, 0.f));
        f = __half22float2(*(__half2*)&a.z);
        *(__half2*)&rs[r][c8 * 8 + 4] = __floats2half2_rn(fmaxf(f.x * iv, 0.f), fmaxf(f.y * iv, 0.f));
        f = __half22float2(*(__half2*)&a.w);
        *(__half2*)&rs[r][c8 * 8 + 6] = __floats2half2_rn(fmaxf(f.x * iv, 0.f), fmaxf(f.y * iv, 0.f));
    }
    // W2 -> ws fp16 (40 rows x 64)
    for (int idx = tid; idx < 640; idx += 256) {
        int r = idx >> 4, c4 = idx & 15;
        float4 v = __ldg((const float4*)(W + (size_t)r * NHID) + c4);
        *(__half2*)&ws[r][c4 * 4]     = __floats2half2_rn(v.x, v.y);
        *(__half2*)&ws[r][c4 * 4 + 2] = __floats2half2_rn(v.z, v.w);
    }
    __syncthreads();

    float acc[5][4];
    #pragma unroll
    for (int j = 0; j < 5; ++j)
        #pragma unroll
        for (int i = 0; i < 4; ++i) acc[j][i] = 0.f;

    #pragma unroll
    for (int kk = 0; kk < 4; ++kk) {
        int k0 = kk * 16;
        unsigned a0, a1, a2, a3;
        {
            int r = m0 + (lane & 7) + ((lane >> 3) & 1) * 8;
            int c = k0 + (lane >> 4) * 8;
            unsigned addr = smem_u32(&rs[r][c]);
            asm volatile(
                "ldmatrix.sync.aligned.m8n8.x4.shared.b16 {%0,%1,%2,%3}, [%4];"
                : "=r"(a0), "=r"(a1), "=r"(a2), "=r"(a3) : "r"(addr));
        }
        #pragma unroll
        for (int l = 0; l < 3; ++l) {     // n0 = 0, 16, 32
            int n0 = l * 16;
            unsigned b0, b1, b2, b3;
            {
                int r = n0 + (lane & 7) + (lane >> 4) * 8;
                int c = k0 + ((lane >> 3) & 1) * 8;
                unsigned addr = smem_u32(&ws[r][c]);
                asm volatile(
                    "ldmatrix.sync.aligned.m8n8.x4.shared.b16 {%0,%1,%2,%3}, [%4];"
                    : "=r"(b0), "=r"(b1), "=r"(b2), "=r"(b3) : "r"(addr));
            }
            float* c0 = acc[l * 2];
            asm volatile(
                "mma.sync.aligned.m16n8k16.row.col.f32.f16.f16.f32 "
                "{%0,%1,%2,%3}, {%4,%5,%6,%7}, {%8,%9}, {%0,%1,%2,%3};"
                : "+f"(c0[0]), "+f"(c0[1]), "+f"(c0[2]), "+f"(c0[3])
                : "r"(a0), "r"(a1), "r"(a2), "r"(a3), "r"(b0), "r"(b1));
            if (l < 2) {                  // 6th n8 tile (n40-47) not needed
                float* c1 = acc[l * 2 + 1];
                asm volatile(
                    "mma.sync.aligned.m16n8k16.row.col.f32.f16.f16.f32 "
                    "{%0,%1,%2,%3}, {%4,%5,%6,%7}, {%8,%9}, {%0,%1,%2,%3};"
                    : "+f"(c1[0]), "+f"(c1[1]), "+f"(c1[2]), "+f"(c1[3])
                    : "r"(a0), "r"(a1), "r"(a2), "r"(a3), "r"(b2), "r"(b3));
            }
        }
    }

    int rA = row0 + m0 + (lane >> 2);
    int rB = rA + 8;
    #pragma unroll
    for (int j = 0; j < 5; ++j) {
        int nn = j * 8 + (lane & 3) * 2;  // 0..39
        float bx = __ldg(&b[nn]), by = __ldg(&b[nn + 1]);
        int wofs = j * 4 + (lane & 3);    // word index 0..19 within 32-word row
        if (rA < n) {
            __half2 h = __floats2half2_rn(acc[j][0] + bx, acc[j][1] + by);
            unsigned wv = *(unsigned*)&h;
            ((unsigned*)g_h2h)[rA * 32 + wofs] = wv;
            ((unsigned*)g_a2h)[rA * 32 + wofs] = wv;
        }
        if (rB < n) {
            __half2 h = __floats2half2_rn(acc[j][2] + bx, acc[j][3] + by);
            unsigned wv = *(unsigned*)&h;
            ((unsigned*)g_h2h)[rB * 32 + wofs] = wv;
            ((unsigned*)g_a2h)[rB * 32 + wofs] = wv;
        }
    }
}

// ====== scatter2: agg2[dst] += h2[src], ILP-4, warp-aligned ==========
// 24 edges/warp: lanes 0-29 in 6 groups of 5; each group: e0,+6,+12,+18.
// Rows are 128B-aligned (8 uint4); group accesses bytes 0..79 of the row.
__global__ __launch_bounds__(256) void k_scatter2(const void* __restrict__ ei, int E) {
    int t = blockIdx.x * blockDim.x + threadIdx.x;
    int warpid = t >> 5;
    int lane = t & 31;
    if (lane >= 30) return;
    int grp = lane / 5, sub = lane - grp * 5;
    int eb = warpid * 24 + grp;
    if (eb >= E) return;

    int s[4], d[4];
    bool ok[4];
    #pragma unroll
    for (int j = 0; j < 4; ++j) {
        int e = eb + j * 6;
        ok[j] = (e < E);
    }
    if (g_is64) {
        const long long* p = (const long long*)ei;
        #pragma unroll
        for (int j = 0; j < 4; ++j) if (ok[j]) {
            int e = eb + j * 6;
            s[j] = (int)__ldg(&p[e]); d[j] = (int)__ldg(&p[E + e]);
        }
    } else {
        const int* p = (const int*)ei;
        #pragma unroll
        for (int j = 0; j < 4; ++j) if (ok[j]) {
            int e = eb + j * 6;
            s[j] = __ldg(&p[e]); d[j] = __ldg(&p[E + e]);
        }
    }
    uint4 v[4];
    #pragma unroll
    for (int j = 0; j < 4; ++j) if (ok[j])
        v[j] = __ldg(&g_h2h[s[j] * 8 + sub]);
    #pragma unroll
    for (int j = 0; j < 4; ++j) if (ok[j])
        asm volatile("red.global.add.noftz.v4.f16x2 [%0], {%1,%2,%3,%4};"
                     :: "l"(&g_a2h[d[j] * 8 + sub]),
                        "r"(v[j].x), "r"(v[j].y), "r"(v[j].z), "r"(v[j].w) : "memory");
}

// ====== finalize: out = log_softmax(agg2/(deg+1))  (warp/row) =========
__global__ __launch_bounds__(256) void k_finalize(float* __restrict__ out, int n) {
    int row  = (blockIdx.x * blockDim.x + threadIdx.x) >> 5;
    int lane = threadIdx.x & 31;
    if (row >= n) return;
    float x0 = -3.4e38f, x1 = -3.4e38f;
    float iv = 1.0f / (float)(g_deg[row] + 1);
    if (lane < 20) {
        unsigned w = ((const unsigned*)g_a2h)[row * 32 + lane];
        float2 f = __half22float2(*(__half2*)&w);
        x0 = f.x * iv; x1 = f.y * iv;
    }
    float m = fmaxf(x0, x1);
    #pragma unroll
    for (int o = 16; o > 0; o >>= 1)
        m = fmaxf(m, __shfl_xor_sync(0xFFFFFFFFu, m, o));
    float s = (lane < 20) ? (expf(x0 - m) + expf(x1 - m)) : 0.f;
    #pragma unroll
    for (int o = 16; o > 0; o >>= 1)
        s += __shfl_xor_sync(0xFFFFFFFFu, s, o);
    float l = m + logf(s);
    if (lane < 20) {
        float2 o2;
        o2.x = x0 - l; o2.y = x1 - l;
        ((float2*)(out + (size_t)row * NCLS))[lane] = o2;
    }
}

// ---------------- launch ----------------
extern "C" void kernel_launch(void* const* d_in, const int* in_sizes, int n_in,
                              void* d_out, int out_size)
{
    const float* x  = (const float*)d_in[0];
    const void*  ei = d_in[1];
    const float* W1 = (const float*)d_in[2];
    const float* b1 = (const float*)d_in[3];
    const float* W2 = (const float*)d_in[4];
    const float* b2 = (const float*)d_in[5];
    float* out = (float*)d_out;

    int n = in_sizes[0] / NFEAT;      // 100000
    int E = in_sizes[1] / 2;          // 1600000

    int w1 = (E + 15) / 16;           // scatter1 warps (16 edges/warp)
    int w2 = (E + 23) / 24;           // scatter2 warps (24 edges/warp)

    k_gemm1   <<<(n + 127) / 128, 256>>>(x, W1, b1, (const unsigned*)ei, n);
    k_scatter1<<<(w1 * 32 + 255) / 256, 256>>>(ei, E);
    k_gemm2   <<<(n + 127) / 128, 256>>>(W2, b2, n);
    k_scatter2<<<(w2 * 32 + 255) / 256, 256>>>(ei, E);
    k_finalize<<<(n + 7) / 8, 256>>>(out, n);
}